// round 1
// baseline (speedup 1.0000x reference)
#include <cuda_runtime.h>

#define T_STEPS 256
#define HCC 64
#define G4 256      // 4*HC
#define PP 55
#define BB 32

// ---------------- scratch (no allocation allowed) ----------------
__device__ float g_feat[2 * BB * 2 * HCC * PP];       // [sub][b][7040] rows=64, K=7040
__device__ float g_y1[64 * 3400];
__device__ float g_y2[64 * 1000];
__device__ float g_y3[64 * 512];
__device__ float g_part[8 * 64 * 3400];               // max KS*64*N

__device__ __forceinline__ float sigm_(float x) {
    return 1.0f / (1.0f + __expf(-x));
}
__device__ __forceinline__ float tanh_(float x) {
    return 2.0f / (1.0f + __expf(-2.0f * x)) - 1.0f;
}

// ---------------- recurrent kernel ----------------
// block = one (sub, cell, b, p) row; thread n owns gate column n (n in [0,256))
__global__ __launch_bounds__(256, 2)
void lstm_kernel(const float* __restrict__ x1, const float* __restrict__ x2,
                 const float* __restrict__ wx1, const float* __restrict__ wh1,
                 const float* __restrict__ bx1, const float* __restrict__ bh1,
                 const float* __restrict__ wx2, const float* __restrict__ wh2,
                 const float* __restrict__ bx2, const float* __restrict__ bh2,
                 float* __restrict__ feat)
{
    int bid = blockIdx.x;
    int p    = bid % PP;
    int b    = (bid / PP) % BB;
    int cell = (bid / (PP * BB)) & 1;
    int sub  = bid / (PP * BB * 2);

    const float* x  = sub  ? x2  : x1;
    const float* wx = cell ? wx2 : wx1;
    const float* wh = cell ? wh2 : wh1;
    const float* bx = cell ? bx2 : bx1;
    const float* bh = cell ? bh2 : bh1;

    int n = threadIdx.x;

    __shared__ float4 hsm4[16];          // h state, 64 floats
    __shared__ float  xrow[T_STEPS * 2]; // x[t][c] for this (b,p)
    __shared__ float  garr[256];
    __shared__ float  act[256];

    // wh column n into registers
    float w[64];
#pragma unroll
    for (int k = 0; k < 64; k++) w[k] = wh[k * G4 + n];
    float wxa  = wx[n];
    float wxb  = wx[G4 + n];
    float bsum = bx[n] + bh[n];

    // prefetch x row: x[((b*T+t)*IC+c)*P + p]
    {
        const float* xb = x + (size_t)b * T_STEPS * 2 * PP + p;
        for (int i = n; i < T_STEPS * 2; i += 256) {
            xrow[i] = xb[(size_t)i * PP];   // i = t*2+c
        }
    }
    if (n < 16) hsm4[n] = make_float4(0.f, 0.f, 0.f, 0.f);
    float cstate = 0.0f;                  // used by threads 0..63
    __syncthreads();

    float* hs = (float*)hsm4;

    for (int t = 0; t < T_STEPS; t++) {
        int tx = cell ? (T_STEPS - 1 - t) : t;
        float g  = bsum + xrow[2 * tx] * wxa + xrow[2 * tx + 1] * wxb;
        float g2 = 0.f;
#pragma unroll
        for (int j = 0; j < 16; j++) {
            float4 hv = hsm4[j];
            g  += hv.x * w[4 * j + 0];
            g2 += hv.y * w[4 * j + 1];
            g  += hv.z * w[4 * j + 2];
            g2 += hv.w * w[4 * j + 3];
        }
        garr[n] = g + g2;
        __syncthreads();

        {
            float v = garr[n];
            act[n] = (n < 192) ? sigm_(v) : tanh_(v);
        }
        __syncthreads();

        if (n < 64) {
            cstate = act[64 + n] * cstate + act[n] * act[192 + n];
            hs[n]  = act[128 + n] * tanh_(cstate);
        }
        __syncthreads();
    }

    // channel-major concat layout: feat[sub][b][cell*HC*P + c*P + p]
    if (n < 64) {
        feat[((size_t)sub * BB + b) * (2 * HCC * PP) + cell * HCC * PP + n * PP + p] = hs[n];
    }
}

// ---------------- FC: K-split GEMM partials + reduce ----------------
// X: (64, K) row-major; W: (K, N); writes Ppart[ks][64][N]
__global__ __launch_bounds__(256)
void gemm_part(const float* __restrict__ X, const float* __restrict__ W,
               float* __restrict__ Ppart, int N, int K, int KS)
{
    int n0 = blockIdx.x * 64;
    int ks = blockIdx.y;
    int k0s = (int)(((long)K * ks) / KS);
    int k1s = (int)(((long)K * (ks + 1)) / KS);

    __shared__ float Asm[64][17];
    __shared__ float Bsm[16][65];

    int tid = threadIdx.x;
    int nl  = tid & 63;
    int mg  = tid >> 6;   // 0..3

    float acc[16];
#pragma unroll
    for (int i = 0; i < 16; i++) acc[i] = 0.f;

    for (int k0 = k0s; k0 < k1s; k0 += 16) {
#pragma unroll
        for (int i = 0; i < 4; i++) {
            int r = (tid >> 4) + i * 16;
            int c = tid & 15;
            int k = k0 + c;
            Asm[r][c] = (k < k1s) ? X[(size_t)r * K + k] : 0.f;
        }
#pragma unroll
        for (int i = 0; i < 4; i++) {
            int r  = (tid >> 6) + i * 4;
            int c  = tid & 63;
            int k  = k0 + r;
            int nn = n0 + c;
            Bsm[r][c] = (k < k1s && nn < N) ? W[(size_t)k * N + nn] : 0.f;
        }
        __syncthreads();
#pragma unroll
        for (int kk = 0; kk < 16; kk++) {
            float bv = Bsm[kk][nl];
#pragma unroll
            for (int i = 0; i < 16; i++)
                acc[i] += Asm[mg * 16 + i][kk] * bv;
        }
        __syncthreads();
    }

    int nn = n0 + nl;
    if (nn < N) {
        float* outp = Ppart + (size_t)ks * 64 * N;
#pragma unroll
        for (int i = 0; i < 16; i++)
            outp[(size_t)(mg * 16 + i) * N + nn] = acc[i];
    }
}

__global__ void reduce_bias(const float* __restrict__ Ppart, const float* __restrict__ bias,
                            float* __restrict__ Y, int N, int KS)
{
    int idx = blockIdx.x * 256 + threadIdx.x;
    if (idx >= 64 * N) return;
    int nn = idx % N;
    float s = bias[nn];
    for (int ks = 0; ks < KS; ks++) s += Ppart[(size_t)ks * 64 * N + idx];
    Y[idx] = s;
}

// ---------------- launch ----------------
extern "C" void kernel_launch(void* const* d_in, const int* in_sizes, int n_in,
                              void* d_out, int out_size)
{
    const float* x1  = (const float*)d_in[0];
    const float* x2  = (const float*)d_in[1];
    const float* wx1 = (const float*)d_in[2];
    const float* wh1 = (const float*)d_in[3];
    const float* bx1 = (const float*)d_in[4];
    const float* bh1 = (const float*)d_in[5];
    const float* wx2 = (const float*)d_in[6];
    const float* wh2 = (const float*)d_in[7];
    const float* bx2 = (const float*)d_in[8];
    const float* bh2 = (const float*)d_in[9];
    const float* fw2 = (const float*)d_in[10];
    const float* fb2 = (const float*)d_in[11];
    const float* fw3 = (const float*)d_in[12];
    const float* fb3 = (const float*)d_in[13];
    const float* fw4 = (const float*)d_in[14];
    const float* fb4 = (const float*)d_in[15];
    const float* fw5 = (const float*)d_in[16];
    const float* fb5 = (const float*)d_in[17];

    float *feat, *y1, *y2, *y3, *part;
    cudaGetSymbolAddress((void**)&feat, g_feat);
    cudaGetSymbolAddress((void**)&y1,   g_y1);
    cudaGetSymbolAddress((void**)&y2,   g_y2);
    cudaGetSymbolAddress((void**)&y3,   g_y3);
    cudaGetSymbolAddress((void**)&part, g_part);

    // recurrent scan: 7040 independent rows
    lstm_kernel<<<2 * 2 * BB * PP, 256>>>(x1, x2, wx1, wh1, bx1, bh1,
                                          wx2, wh2, bx2, bh2, feat);

    // FC1: 7040 -> 3400
    gemm_part<<<dim3(54, 8), 256>>>(feat, fw2, part, 3400, 7040, 8);
    reduce_bias<<<(64 * 3400 + 255) / 256, 256>>>(part, fb2, y1, 3400, 8);
    // FC2: 3400 -> 1000
    gemm_part<<<dim3(16, 8), 256>>>(y1, fw3, part, 1000, 3400, 8);
    reduce_bias<<<(64 * 1000 + 255) / 256, 256>>>(part, fb3, y2, 1000, 8);
    // FC3: 1000 -> 500
    gemm_part<<<dim3(8, 4), 256>>>(y2, fw4, part, 500, 1000, 4);
    reduce_bias<<<(64 * 500 + 255) / 256, 256>>>(part, fb4, y3, 500, 4);
    // FC4: 500 -> 50 -> d_out (out1 rows 0..31, out2 rows 32..63)
    gemm_part<<<dim3(1, 2), 256>>>(y3, fw5, part, 50, 500, 2);
    reduce_bias<<<(64 * 50 + 255) / 256, 256>>>(part, fb5, (float*)d_out, 50, 2);
}